// round 2
// baseline (speedup 1.0000x reference)
#include <cuda_runtime.h>
#include <cuda_bf16.h>
#include <cstdint>

#define NPTS 65536
#define NE 8
#define DIN 90
#define NH 256
#define DOUT 4
#define XROW 93           // 3 xyz + 90 feats
#define TILE_P 64
#define FPAD 92           // DIN padded to even, 8B-aligned rows
#define MLP_THREADS 512
#define MLP_BLOCKS (NE * (NPTS / TILE_P))   // 8 * 1024 = 8192

// -------- scratch (device globals; no allocation allowed) --------
__device__ float g_w[NPTS * NE];       // routing weights
__device__ int   g_idx[NE * NPTS];     // per-expert compacted point lists
__device__ int   g_cnt[NE];            // per-expert counts

// -------- packed f32x2 helpers --------
__device__ __forceinline__ unsigned long long ffma2(unsigned long long a,
                                                    unsigned long long b,
                                                    unsigned long long c) {
    unsigned long long d;
    asm("fma.rn.f32x2 %0, %1, %2, %3;" : "=l"(d) : "l"(a), "l"(b), "l"(c));
    return d;
}
__device__ __forceinline__ unsigned long long packf2(float lo, float hi) {
    unsigned long long d;
    asm("mov.b64 %0, {%1, %2};" : "=l"(d) : "f"(lo), "f"(hi));
    return d;
}
__device__ __forceinline__ float2 unpackf2(unsigned long long a) {
    float lo, hi;
    asm("mov.b64 {%0, %1}, %2;" : "=f"(lo), "=f"(hi) : "l"(a));
    return make_float2(lo, hi);
}

// -------- kernel 0: zero per-expert counters --------
__global__ void zero_cnt_kernel() {
    if (threadIdx.x < NE) g_cnt[threadIdx.x] = 0;
}

// -------- kernel 1: routing + compaction + output zero --------
__global__ void routing_kernel(const float* __restrict__ x,
                               const float* __restrict__ cent,
                               float* __restrict__ out) {
    int n = blockIdx.x * blockDim.x + threadIdx.x;
    if (n >= NPTS) return;
    const float px = x[n * XROW + 0];
    const float py = x[n * XROW + 1];
    const float pz = x[n * XROW + 2];

    float d[NE];
    float dmin = 3.4e38f;
#pragma unroll
    for (int e = 0; e < NE; e++) {
        float dx = px - cent[e * 3 + 0];
        float dy = py - cent[e * 3 + 1];
        float dz = pz - cent[e * 3 + 2];
        d[e] = sqrtf(dx * dx + dy * dy + dz * dz);
        dmin = fminf(dmin, d[e]);
    }
    float inv[NE];
    float s = 0.f;
#pragma unroll
    for (int e = 0; e < NE; e++) {
        float v = 1.0f / (d[e] + 1e-8f);
        if (d[e] > 2.0f * dmin) v = 0.f;
        inv[e] = v;
        s += v;
    }
    float rs = 1.0f / s;
#pragma unroll
    for (int e = 0; e < NE; e++) {
        float w = inv[e] * rs;
        g_w[n * NE + e] = w;
        if (w > 0.f) {
            int pos = atomicAdd(&g_cnt[e], 1);
            g_idx[e * NPTS + pos] = n;
        }
    }
    // zero output row (out is poisoned by the harness)
    *reinterpret_cast<float4*>(out + n * 4) = make_float4(0.f, 0.f, 0.f, 0.f);
}

// -------- kernel 2: fused 3-layer MLP per (expert, 64-point chunk) --------
// smem: F[64][92] | H1[64][256] | H2[64][256] | idx[64]
#define SMEM_FLOATS (TILE_P * FPAD + TILE_P * NH + TILE_P * NH + TILE_P)

__global__ __launch_bounds__(MLP_THREADS, 1)
void mlp_kernel(const float* __restrict__ x,
                const float* __restrict__ W1, const float* __restrict__ b1,
                const float* __restrict__ W2, const float* __restrict__ b2,
                const float* __restrict__ W3, const float* __restrict__ b3,
                float* __restrict__ out) {
    const int e = blockIdx.x & (NE - 1);
    const int c = blockIdx.x >> 3;
    const int cnt = g_cnt[e];
    const int base = c * TILE_P;
    if (base >= cnt) return;
    const int np = min(TILE_P, cnt - base);

    extern __shared__ float smem[];
    float* sF  = smem;                        // 64 x 92
    float* sH1 = sF + TILE_P * FPAD;          // 64 x 256
    float* sH2 = sH1 + TILE_P * NH;           // 64 x 256
    int*   sIdx = (int*)(sH2 + TILE_P * NH);  // 64

    const int t = threadIdx.x;
    if (t < TILE_P) sIdx[t] = (t < np) ? g_idx[e * NPTS + base + t] : 0;
    __syncthreads();

    // gather features (zero-pad k>=90 and p>=np)
    for (int i = t; i < TILE_P * FPAD; i += MLP_THREADS) {
        int p = i / FPAD;
        int k = i - p * FPAD;
        float v = 0.f;
        if (k < DIN && p < np) v = x[sIdx[p] * XROW + 3 + k];
        sF[i] = v;
    }
    __syncthreads();

    const int j  = t & (NH - 1);   // hidden column
    const int ph = t >> 8;         // point half (0/1)
    const int p0 = ph * 32;

    // ---- layer 1: h1 = relu(F @ W1 + b1) ----
    unsigned long long acc[32];
#pragma unroll
    for (int i = 0; i < 32; i++) acc[i] = 0ULL;

    const float* Wp1 = W1 + (e * DIN) * NH + j;
    const unsigned long long* F2 = (const unsigned long long*)sF;  // row stride FPAD/2
    for (int kp = 0; kp < DIN / 2; kp++) {
        float w0 = Wp1[(2 * kp) * NH];
        float w1 = Wp1[(2 * kp + 1) * NH];
        unsigned long long wp = packf2(w0, w1);
#pragma unroll
        for (int pi = 0; pi < 32; pi++) {
            acc[pi] = ffma2(F2[(p0 + pi) * (FPAD / 2) + kp], wp, acc[pi]);
        }
    }
    {
        float b1j = b1[e * NH + j];
#pragma unroll
        for (int pi = 0; pi < 32; pi++) {
            float2 v = unpackf2(acc[pi]);
            float h = v.x + v.y + b1j;
            sH1[(p0 + pi) * NH + j] = fmaxf(h, 0.f);
        }
    }
    __syncthreads();

    // ---- layer 2: h2 = relu(H1 @ W2 + b2) ----
#pragma unroll
    for (int i = 0; i < 32; i++) acc[i] = 0ULL;

    const float* Wp2 = W2 + (e * NH) * NH + j;
    const ulonglong2* H14 = (const ulonglong2*)sH1;  // p*64 + kg
    for (int kg = 0; kg < NH / 4; kg++) {
        int k = 4 * kg;
        float w0 = Wp2[(k + 0) * NH];
        float w1 = Wp2[(k + 1) * NH];
        float w2 = Wp2[(k + 2) * NH];
        float w3 = Wp2[(k + 3) * NH];
        unsigned long long wp01 = packf2(w0, w1);
        unsigned long long wp23 = packf2(w2, w3);
#pragma unroll
        for (int pi = 0; pi < 32; pi++) {
            ulonglong2 h = H14[(p0 + pi) * (NH / 4) + kg];
            acc[pi] = ffma2(h.x, wp01, acc[pi]);
            acc[pi] = ffma2(h.y, wp23, acc[pi]);
        }
    }
    {
        float b2j = b2[e * NH + j];
#pragma unroll
        for (int pi = 0; pi < 32; pi++) {
            float2 v = unpackf2(acc[pi]);
            float h = v.x + v.y + b2j;
            sH2[(p0 + pi) * NH + j] = fmaxf(h, 0.f);
        }
    }
    __syncthreads();

    // ---- layer 3 + weighted scatter: out += w * (H2 @ W3 + b3) ----
    if (t < TILE_P * DOUT) {
        int p = t >> 2;
        int o = t & 3;
        const float* Wp3 = W3 + (e * NH) * DOUT + o;
        float acc3 = b3[e * DOUT + o];
        int ks = (p * 4) & (NH - 1);   // rotate start -> conflict-free smem reads
#pragma unroll 4
        for (int i = 0; i < NH; i++) {
            int k = (ks + i) & (NH - 1);
            acc3 += sH2[p * NH + k] * Wp3[k * DOUT];
        }
        if (p < np) {
            int n = sIdx[p];
            float wgt = g_w[n * NE + e];
            atomicAdd(&out[n * 4 + o], wgt * acc3);
        }
    }
}

// -------- launch --------
extern "C" void kernel_launch(void* const* d_in, const int* in_sizes, int n_in,
                              void* d_out, int out_size) {
    const float* x    = (const float*)d_in[0];
    const float* cent = (const float*)d_in[1];
    const float* W1   = (const float*)d_in[2];
    const float* b1   = (const float*)d_in[3];
    const float* W2   = (const float*)d_in[4];
    const float* b2   = (const float*)d_in[5];
    const float* W3   = (const float*)d_in[6];
    const float* b3   = (const float*)d_in[7];
    float* out = (float*)d_out;

    // Immediate host-side call (not a stream op) — safe under graph capture,
    // idempotent, no static guard needed.
    cudaFuncSetAttribute(mlp_kernel, cudaFuncAttributeMaxDynamicSharedMemorySize,
                         SMEM_FLOATS * (int)sizeof(float));

    zero_cnt_kernel<<<1, 32>>>();
    routing_kernel<<<NPTS / 256, 256>>>(x, cent, out);
    mlp_kernel<<<MLP_BLOCKS, MLP_THREADS, SMEM_FLOATS * (int)sizeof(float)>>>(
        x, W1, b1, W2, b2, W3, b3, out);
}

// round 4
// speedup vs baseline: 2.3427x; 2.3427x over previous
#include <cuda_runtime.h>
#include <cstdint>

#define NPTS 65536
#define NE 8
#define DIN 90
#define NH 256
#define DOUT 4
#define XROW 93
#define TILE_P 128
#define KPAD 96
#define THREADS 512
#define BLOCKS (NE * (NPTS / TILE_P))   // 4096

#define KP1 100   // float stride for F / W1s rows (k up to 96)
#define KP2 260   // float stride for H1 / W2c rows (k up to 256)

// smem offsets in floats
#define SF    0                    // F [128][100]
#define SW1   (128 * KP1)          // W1s [256][100]
#define SH1   0                    // H1 [128][260] overlays F+W1s after L1
#define SW2   (SW1 + 256 * KP1)    // W2c [64][260]
#define SB1   (SW2 + 64 * KP2)     // b1 [256]
#define SB2   (SB1 + 256)          // b2 [256]
#define SW3T  (SB2 + 256)          // W3 [256][4]
#define SB3   (SW3T + 1024)        // b3 [4] (+pad)
#define SIDX  (SB3 + 8)            // idx [128] ints
#define SPART 0                    // partials [4][128][4], overlays H1 at the end
#define SMEM_FLOATS (SIDX + 128)
#define SMEM_BYTES  (SMEM_FLOATS * 4)

// -------- scratch --------
__device__ float g_w[NPTS * NE];
__device__ int   g_idx[NE * NPTS];
__device__ int   g_cnt[NE];

__device__ __forceinline__ float tf32r(float x) {
    uint32_t u;
    asm("cvt.rna.tf32.f32 %0, %1;" : "=r"(u) : "f"(x));
    return __uint_as_float(u);
}

// m16n8k8 tf32 mma: D += A*B (fp32 accum)
__device__ __forceinline__ void mma8(float& c0, float& c1, float& c2, float& c3,
                                     uint32_t a0, uint32_t a1, uint32_t a2, uint32_t a3,
                                     uint32_t b0, uint32_t b1) {
    asm volatile(
        "mma.sync.aligned.m16n8k8.row.col.f32.tf32.tf32.f32 "
        "{%0,%1,%2,%3}, {%4,%5,%6,%7}, {%8,%9}, {%0,%1,%2,%3};"
        : "+f"(c0), "+f"(c1), "+f"(c2), "+f"(c3)
        : "r"(a0), "r"(a1), "r"(a2), "r"(a3), "r"(b0), "r"(b1));
}

// -------- kernel 0/1: counters + routing (validated in R2) --------
__global__ void zero_cnt_kernel() {
    if (threadIdx.x < NE) g_cnt[threadIdx.x] = 0;
}

__global__ void routing_kernel(const float* __restrict__ x,
                               const float* __restrict__ cent,
                               float* __restrict__ out) {
    int n = blockIdx.x * blockDim.x + threadIdx.x;
    if (n >= NPTS) return;
    const float px = x[n * XROW + 0];
    const float py = x[n * XROW + 1];
    const float pz = x[n * XROW + 2];
    float d[NE];
    float dmin = 3.4e38f;
#pragma unroll
    for (int e = 0; e < NE; e++) {
        float dx = px - cent[e * 3 + 0];
        float dy = py - cent[e * 3 + 1];
        float dz = pz - cent[e * 3 + 2];
        d[e] = sqrtf(dx * dx + dy * dy + dz * dz);
        dmin = fminf(dmin, d[e]);
    }
    float inv[NE];
    float s = 0.f;
#pragma unroll
    for (int e = 0; e < NE; e++) {
        float v = 1.0f / (d[e] + 1e-8f);
        if (d[e] > 2.0f * dmin) v = 0.f;
        inv[e] = v;
        s += v;
    }
    float rs = 1.0f / s;
#pragma unroll
    for (int e = 0; e < NE; e++) {
        float w = inv[e] * rs;
        g_w[n * NE + e] = w;
        if (w > 0.f) {
            int pos = atomicAdd(&g_cnt[e], 1);
            g_idx[e * NPTS + pos] = n;
        }
    }
    *reinterpret_cast<float4*>(out + n * 4) = make_float4(0.f, 0.f, 0.f, 0.f);
}

// -------- kernel 2: HMMA tf32 fused MLP --------
__global__ __launch_bounds__(THREADS, 1)
void mlp_mma_kernel(const float* __restrict__ x,
                    const float* __restrict__ W1, const float* __restrict__ b1,
                    const float* __restrict__ W2, const float* __restrict__ b2,
                    const float* __restrict__ W3, const float* __restrict__ b3,
                    float* __restrict__ out) {
    const int e = blockIdx.x & (NE - 1);
    const int c = blockIdx.x >> 3;
    const int cnt = g_cnt[e];
    const int base = c * TILE_P;
    if (base >= cnt) return;
    const int np = min(TILE_P, cnt - base);

    extern __shared__ float sm[];
    int* sIdx = (int*)(sm + SIDX);

    const int t = threadIdx.x;
    const int wid = t >> 5;
    const int lane = t & 31;
    const int g = lane >> 2;       // group id 0..7
    const int tg = lane & 3;       // thread-in-group 0..3
    const int mg = wid & 3;        // m-group: rows mg*32..+32
    const int ng = wid >> 2;       // n-group

    if (t < TILE_P) sIdx[t] = (t < np) ? g_idx[e * NPTS + base + t] : 0;
    if (t < NH) sm[SB1 + t] = b1[e * NH + t];
    if (t < NH) sm[SB2 + t] = b2[e * NH + t];
    if (t < DOUT) sm[SB3 + t] = b3[e * DOUT + t];
    for (int i = t; i < NH * DOUT; i += THREADS) sm[SW3T + i] = W3[e * NH * DOUT + i];
    __syncthreads();

    // ---- load F [128][KP1] (tf32-rounded, zero-padded) ----
    {
        const int p = t >> 2, kq = t & 3;
        const int n = sIdx[p];
        const float* xr = x + (size_t)n * XROW + 3;
#pragma unroll
        for (int kk = 0; kk < KP1 / 4; kk++) {
            int k = kq * (KP1 / 4) + kk;
            float v = (p < np && k < DIN) ? tf32r(xr[k]) : 0.f;
            sm[SF + p * KP1 + k] = v;
        }
    }
    // ---- load W1s [256][KP1]: W1s[n][k] = W1[e][k][n] ----
    {
        const float* W1e = W1 + (size_t)e * DIN * NH;
        for (int i = t; i < NH * KP1; i += THREADS) {
            int n = i / KP1, k = i - n * KP1;
            sm[SW1 + n * KP1 + k] = (k < DIN) ? tf32r(W1e[k * NH + n]) : 0.f;
        }
    }
    __syncthreads();

    // ---- layer 1: each warp computes C[32][64] = F[mg*32..][.] @ W1^T cols ng*64.. ----
    {
        float acc[2][8][4];
#pragma unroll
        for (int mt = 0; mt < 2; mt++)
#pragma unroll
            for (int nt = 0; nt < 8; nt++)
#pragma unroll
                for (int r = 0; r < 4; r++) acc[mt][nt][r] = 0.f;

        const int m0 = mg * 32;
        const int n0 = ng * 64;
        for (int k0 = 0; k0 < KPAD; k0 += 8) {
            uint32_t a[2][4];
#pragma unroll
            for (int mt = 0; mt < 2; mt++) {
                const float* Ar = sm + SF + (m0 + mt * 16 + g) * KP1 + k0;
                a[mt][0] = __float_as_uint(Ar[tg]);
                a[mt][1] = __float_as_uint(Ar[8 * KP1 + tg]);
                a[mt][2] = __float_as_uint(Ar[tg + 4]);
                a[mt][3] = __float_as_uint(Ar[8 * KP1 + tg + 4]);
            }
#pragma unroll
            for (int nt = 0; nt < 8; nt++) {
                const float* Br = sm + SW1 + (n0 + nt * 8 + g) * KP1 + k0;
                uint32_t b0 = __float_as_uint(Br[tg]);
                uint32_t b1r = __float_as_uint(Br[tg + 4]);
#pragma unroll
                for (int mt = 0; mt < 2; mt++)
                    mma8(acc[mt][nt][0], acc[mt][nt][1], acc[mt][nt][2], acc[mt][nt][3],
                         a[mt][0], a[mt][1], a[mt][2], a[mt][3], b0, b1r);
            }
        }
        __syncthreads();   // all warps done reading F/W1s before H1 overlay

        // epilogue 1: H1 = tf32(relu(C + b1))
#pragma unroll
        for (int mt = 0; mt < 2; mt++) {
#pragma unroll
            for (int nt = 0; nt < 8; nt++) {
                int col = n0 + nt * 8 + 2 * tg;
                float bb0 = sm[SB1 + col], bb1 = sm[SB1 + col + 1];
                int r0 = m0 + mt * 16 + g;
                sm[SH1 + r0 * KP2 + col]           = tf32r(fmaxf(acc[mt][nt][0] + bb0, 0.f));
                sm[SH1 + r0 * KP2 + col + 1]       = tf32r(fmaxf(acc[mt][nt][1] + bb1, 0.f));
                sm[SH1 + (r0 + 8) * KP2 + col]     = tf32r(fmaxf(acc[mt][nt][2] + bb0, 0.f));
                sm[SH1 + (r0 + 8) * KP2 + col + 1] = tf32r(fmaxf(acc[mt][nt][3] + bb1, 0.f));
            }
        }
    }
    __syncthreads();

    // ---- layer 2 (4 N-chunks of 64) + fused layer 3 partials ----
    float part[4][4];   // [row r: g+8r][out o]
#pragma unroll
    for (int r = 0; r < 4; r++)
#pragma unroll
        for (int o = 0; o < 4; o++) part[r][o] = 0.f;

    const float* W2e = W2 + (size_t)e * NH * NH;
    const int m0 = mg * 32;
    for (int n2 = 0; n2 < 4; n2++) {
        // load W2c [64][260]: W2c[n][k] = W2[e][k][n2*64+n]
        for (int i = t; i < 64 * NH; i += THREADS) {
            int n = i & 63, k = i >> 6;
            sm[SW2 + n * KP2 + k] = tf32r(W2e[k * NH + n2 * 64 + n]);
        }
        __syncthreads();

        float acc[2][2][4];
#pragma unroll
        for (int mt = 0; mt < 2; mt++)
#pragma unroll
            for (int nt = 0; nt < 2; nt++)
#pragma unroll
                for (int r = 0; r < 4; r++) acc[mt][nt][r] = 0.f;

        const int nn0 = ng * 16;
        for (int k0 = 0; k0 < NH; k0 += 8) {
            uint32_t a[2][4];
#pragma unroll
            for (int mt = 0; mt < 2; mt++) {
                const float* Ar = sm + SH1 + (m0 + mt * 16 + g) * KP2 + k0;
                a[mt][0] = __float_as_uint(Ar[tg]);
                a[mt][1] = __float_as_uint(Ar[8 * KP2 + tg]);
                a[mt][2] = __float_as_uint(Ar[tg + 4]);
                a[mt][3] = __float_as_uint(Ar[8 * KP2 + tg + 4]);
            }
#pragma unroll
            for (int nt = 0; nt < 2; nt++) {
                const float* Br = sm + SW2 + (nn0 + nt * 8 + g) * KP2 + k0;
                uint32_t b0 = __float_as_uint(Br[tg]);
                uint32_t b1r = __float_as_uint(Br[tg + 4]);
#pragma unroll
                for (int mt = 0; mt < 2; mt++)
                    mma8(acc[mt][nt][0], acc[mt][nt][1], acc[mt][nt][2], acc[mt][nt][3],
                         a[mt][0], a[mt][1], a[mt][2], a[mt][3], b0, b1r);
            }
        }

        // fuse: part[row][o] += relu(c + b2[j]) * W3[j][o]
#pragma unroll
        for (int mt = 0; mt < 2; mt++) {
#pragma unroll
            for (int nt = 0; nt < 2; nt++) {
#pragma unroll
                for (int cc = 0; cc < 4; cc++) {
                    int j = n2 * 64 + nn0 + nt * 8 + 2 * tg + (cc & 1);
                    int r = mt * 2 + (cc >> 1);     // row = m0 + g + (cc>=2?8:0) + mt*16
                    float h = fmaxf(acc[mt][nt][cc] + sm[SB2 + j], 0.f);
#pragma unroll
                    for (int o = 0; o < 4; o++)
                        part[r][o] = fmaf(h, sm[SW3T + j * 4 + o], part[r][o]);
                }
            }
        }
        __syncthreads();   // W2c reusable next chunk
    }

    // ---- reduce across tg (4 lanes) then across ng warps via smem ----
#pragma unroll
    for (int r = 0; r < 4; r++)
#pragma unroll
        for (int o = 0; o < 4; o++) {
            part[r][o] += __shfl_xor_sync(0xFFFFFFFFu, part[r][o], 1);
            part[r][o] += __shfl_xor_sync(0xFFFFFFFFu, part[r][o], 2);
        }
    // rows held by this thread: m0 + g + {0,8} + mt*16  -> r=mt*2+hi : row = m0 + mt*16 + hi*8 + g
    if (tg == 0) {
#pragma unroll
        for (int r = 0; r < 4; r++) {
            int row = m0 + (r >> 1) * 16 + (r & 1) * 8 + g;
#pragma unroll
            for (int o = 0; o < 4; o++)
                sm[SPART + ((ng * TILE_P) + row) * 4 + o] = part[r][o];
        }
    }
    __syncthreads();

    // ---- final: out[n] += w * (sum_ng part + b3) ----
    {
        const int p = t >> 2, o = t & 3;
        float v = sm[SB3 + o];
#pragma unroll
        for (int q = 0; q < 4; q++) v += sm[SPART + ((q * TILE_P) + p) * 4 + o];
        if (p < np) {
            int n = sIdx[p];
            atomicAdd(&out[n * 4 + o], g_w[n * NE + e] * v);
        }
    }
}

// -------- launch --------
extern "C" void kernel_launch(void* const* d_in, const int* in_sizes, int n_in,
                              void* d_out, int out_size) {
    const float* x    = (const float*)d_in[0];
    const float* cent = (const float*)d_in[1];
    const float* W1   = (const float*)d_in[2];
    const float* b1   = (const float*)d_in[3];
    const float* W2   = (const float*)d_in[4];
    const float* b2   = (const float*)d_in[5];
    const float* W3   = (const float*)d_in[6];
    const float* b3   = (const float*)d_in[7];
    float* out = (float*)d_out;

    cudaFuncSetAttribute(mlp_mma_kernel, cudaFuncAttributeMaxDynamicSharedMemorySize,
                         SMEM_BYTES);

    zero_cnt_kernel<<<1, 32>>>();
    routing_kernel<<<NPTS / 256, 256>>>(x, cent, out);
    mlp_mma_kernel<<<BLOCKS, THREADS, SMEM_BYTES>>>(x, W1, b1, W2, b2, W3, b3, out);
}

// round 5
// speedup vs baseline: 6.3367x; 2.7048x over previous
#include <cuda_runtime.h>
#include <cuda_fp16.h>
#include <cstdint>

#define NPTS 65536
#define NE 8
#define DIN 90
#define NH 256
#define DOUT 4
#define XROW 93
#define TILE_P 128
#define KPAD 96
#define THREADS 512
#define BLOCKS (NE * (NPTS / TILE_P))   // 4096

// smem byte offsets; row strides 208B (13*16) and 528B (33*16): odd*16 => ldmatrix conflict-free
#define SH_F    0          // F [128][104h]  (26,624B)
#define SH_W1   26624      // W1T [256][104h] (53,248B)  | H1 [128][264h] overlays at 0 (67,584B)
#define SH_H1   0
#define SH_W2   79872      // W2T [256][264h] (135,168B)
#define SH_B1   215040     // b1 fp32 [256]
#define SH_B2   216064     // b2 fp32 [256]
#define SH_W3   217088     // W3 fp32 [256][4]
#define SH_B3   221184     // b3 fp32 [4]
#define SH_IDX  221200     // idx [128] int
#define SH_PART 221712     // partials [4][128][4] fp32 (8,192B)
#define SMEM_BYTES 229920

// -------- device scratch --------
__device__ float  g_w[NPTS * NE];
__device__ int    g_idx[NE * NPTS];
__device__ int    g_cnt[NE];
__device__ __half g_xh[NPTS * KPAD];            // x feats, fp16, padded to 96
__device__ __half g_w1t[NE * NH * KPAD];        // [e][n][k]
__device__ __half g_w2t[NE * NH * NH];          // [e][n][k]

#define CONV_TOTAL (NPTS * KPAD + NE * NH * KPAD + NE * NH * NH)

// -------- PTX helpers --------
__device__ __forceinline__ uint32_t smem_u32(const void* p) {
    uint32_t a;
    asm("{ .reg .u64 t; cvta.to.shared.u64 t, %1; cvt.u32.u64 %0, t; }" : "=r"(a) : "l"(p));
    return a;
}
__device__ __forceinline__ void ldsm4(uint32_t& r0, uint32_t& r1, uint32_t& r2, uint32_t& r3,
                                      uint32_t addr) {
    asm volatile("ldmatrix.sync.aligned.m8n8.x4.shared.b16 {%0,%1,%2,%3}, [%4];"
                 : "=r"(r0), "=r"(r1), "=r"(r2), "=r"(r3) : "r"(addr));
}
__device__ __forceinline__ void mma16816(float* c, const uint32_t* a, uint32_t b0, uint32_t b1) {
    asm volatile(
        "mma.sync.aligned.m16n8k16.row.col.f32.f16.f16.f32 "
        "{%0,%1,%2,%3}, {%4,%5,%6,%7}, {%8,%9}, {%0,%1,%2,%3};"
        : "+f"(c[0]), "+f"(c[1]), "+f"(c[2]), "+f"(c[3])
        : "r"(a[0]), "r"(a[1]), "r"(a[2]), "r"(a[3]), "r"(b0), "r"(b1));
}
__device__ __forceinline__ void cpa16(uint32_t dst, const void* src) {
    asm volatile("cp.async.cg.shared.global [%0], [%1], 16;" :: "r"(dst), "l"(src));
}
__device__ __forceinline__ void cpa_commit() { asm volatile("cp.async.commit_group;"); }
__device__ __forceinline__ void cpa_wait1() { asm volatile("cp.async.wait_group 1;" ::: "memory"); }
__device__ __forceinline__ void cpa_wait0() { asm volatile("cp.async.wait_group 0;" ::: "memory"); }

// -------- kernel 0: counters --------
__global__ void zero_cnt_kernel() {
    if (threadIdx.x < NE) g_cnt[threadIdx.x] = 0;
}

// -------- kernel 1: routing + compaction + out zero --------
__global__ void routing_kernel(const float* __restrict__ x,
                               const float* __restrict__ cent,
                               float* __restrict__ out) {
    int n = blockIdx.x * blockDim.x + threadIdx.x;
    if (n >= NPTS) return;
    const float px = x[n * XROW + 0];
    const float py = x[n * XROW + 1];
    const float pz = x[n * XROW + 2];
    float d[NE];
    float dmin = 3.4e38f;
#pragma unroll
    for (int e = 0; e < NE; e++) {
        float dx = px - cent[e * 3 + 0];
        float dy = py - cent[e * 3 + 1];
        float dz = pz - cent[e * 3 + 2];
        d[e] = sqrtf(dx * dx + dy * dy + dz * dz);
        dmin = fminf(dmin, d[e]);
    }
    float inv[NE];
    float s = 0.f;
#pragma unroll
    for (int e = 0; e < NE; e++) {
        float v = 1.0f / (d[e] + 1e-8f);
        if (d[e] > 2.0f * dmin) v = 0.f;
        inv[e] = v;
        s += v;
    }
    float rs = 1.0f / s;
#pragma unroll
    for (int e = 0; e < NE; e++) {
        float w = inv[e] * rs;
        g_w[n * NE + e] = w;
        if (w > 0.f) {
            int pos = atomicAdd(&g_cnt[e], 1);
            g_idx[e * NPTS + pos] = n;
        }
    }
    *reinterpret_cast<float4*>(out + n * 4) = make_float4(0.f, 0.f, 0.f, 0.f);
}

// -------- kernel 1b: fp16 pre-convert (x feats, W1T, W2T) --------
__global__ void convert_kernel(const float* __restrict__ x,
                               const float* __restrict__ W1,
                               const float* __restrict__ W2) {
    int i = blockIdx.x * blockDim.x + threadIdx.x;
    if (i < NPTS * KPAD) {
        int n = i / KPAD, k = i - n * KPAD;
        g_xh[i] = (k < DIN) ? __float2half_rn(x[n * XROW + 3 + k]) : __half(0.f);
    } else if (i < NPTS * KPAD + NE * NH * KPAD) {
        int r = i - NPTS * KPAD;
        int e = r / (NH * KPAD);
        int rr = r - e * NH * KPAD;
        int n = rr / KPAD, k = rr - n * KPAD;
        g_w1t[r] = (k < DIN) ? __float2half_rn(W1[(e * DIN + k) * NH + n]) : __half(0.f);
    } else if (i < CONV_TOTAL) {
        int r = i - NPTS * KPAD - NE * NH * KPAD;
        int e = r >> 16;
        int rr = r & 65535;
        int n = rr >> 8, k = rr & 255;
        g_w2t[r] = __float2half_rn(W2[(e << 16) + (k << 8) + n]);
    }
}

// -------- kernel 2: fp16 HMMA fused MLP --------
__global__ __launch_bounds__(THREADS, 1)
void mlp_mma_kernel(const float* __restrict__ b1, const float* __restrict__ b2,
                    const float* __restrict__ W3, const float* __restrict__ b3,
                    float* __restrict__ out) {
    const int e = blockIdx.x & (NE - 1);
    const int c = blockIdx.x >> 3;
    const int cnt = g_cnt[e];
    const int base = c * TILE_P;
    if (base >= cnt) return;
    const int np = min(TILE_P, cnt - base);

    extern __shared__ char smb[];
    const uint32_t A0 = smem_u32(smb);
    float* smf = (float*)smb;
    int* sIdx = (int*)(smb + SH_IDX);

    const int t = threadIdx.x;
    const int wid = t >> 5;
    const int lane = t & 31;
    const int g = lane >> 2;
    const int tg = lane & 3;
    const int mg = wid & 3;
    const int ng = wid >> 2;
    const int m0 = mg * 32;
    const int n0 = ng * 64;

    if (t < TILE_P) sIdx[t] = (t < np) ? g_idx[e * NPTS + base + t] : 0;
    if (t < NH) smf[SH_B1 / 4 + t] = b1[e * NH + t];
    if (t < NH) smf[SH_B2 / 4 + t] = b2[e * NH + t];
    if (t < DOUT) smf[SH_B3 / 4 + t] = b3[e * DOUT + t];
    for (int i = t; i < NH * DOUT; i += THREADS) smf[SH_W3 / 4 + i] = W3[e * NH * DOUT + i];
    __syncthreads();

    // ---- group0: F gather (4 thr/row x 3 chunks) + W1T (2 thr/row x 6) ----
    {
        int p = t >> 2;
        const char* src = (const char*)(g_xh + (size_t)sIdx[p] * KPAD);
        uint32_t dst = A0 + SH_F + p * 208;
        int o0 = (t & 3) * 3;
#pragma unroll
        for (int j = 0; j < 3; j++) cpa16(dst + (o0 + j) * 16, src + (o0 + j) * 16);
    }
    {
        int n = t >> 1;
        const char* src = (const char*)(g_w1t + ((size_t)e * NH + n) * KPAD);
        uint32_t dst = A0 + SH_W1 + n * 208;
        int o0 = (t & 1) * 6;
#pragma unroll
        for (int j = 0; j < 6; j++) cpa16(dst + (o0 + j) * 16, src + (o0 + j) * 16);
    }
    cpa_commit();
    // ---- group1: W2T (2 thr/row x 16 chunks), hidden behind layer 1 ----
    {
        int n = t >> 1;
        const char* src = (const char*)(g_w2t + ((size_t)e * NH + n) * NH);
        uint32_t dst = A0 + SH_W2 + n * 528;
        int o0 = (t & 1) * 16;
#pragma unroll
        for (int j = 0; j < 16; j++) cpa16(dst + (o0 + j) * 16, src + (o0 + j) * 16);
    }
    cpa_commit();
    cpa_wait1();
    __syncthreads();

    // ---- layer 1: C[32][64] per warp, K=96 ----
    float acc[2][8][4];
#pragma unroll
    for (int mt = 0; mt < 2; mt++)
#pragma unroll
        for (int nt = 0; nt < 8; nt++)
#pragma unroll
            for (int r = 0; r < 4; r++) acc[mt][nt][r] = 0.f;
    {
        const uint32_t aBase = A0 + SH_F + (m0 + (lane & 15)) * 208 + (lane >> 4) * 16;
        const uint32_t bBase = A0 + SH_W1 + (n0 + (lane & 7) + (lane >> 4) * 8) * 208 +
                               ((lane >> 3) & 1) * 16;
#pragma unroll
        for (int ks = 0; ks < KPAD / 16; ks++) {
            const int k2 = ks * 32;   // k0*2 bytes
            uint32_t a[2][4];
            ldsm4(a[0][0], a[0][1], a[0][2], a[0][3], aBase + k2);
            ldsm4(a[1][0], a[1][1], a[1][2], a[1][3], aBase + 16 * 208 + k2);
#pragma unroll
            for (int q = 0; q < 4; q++) {
                uint32_t b0, b1r, b2r, b3r;
                ldsm4(b0, b1r, b2r, b3r, bBase + q * 16 * 208 + k2);
                mma16816(acc[0][2 * q], a[0], b0, b1r);
                mma16816(acc[1][2 * q], a[1], b0, b1r);
                mma16816(acc[0][2 * q + 1], a[0], b2r, b3r);
                mma16816(acc[1][2 * q + 1], a[1], b2r, b3r);
            }
        }
    }
    __syncthreads();   // everyone done reading F/W1T before H1 overlay

    // ---- epilogue 1: H1 = half(relu(C + b1)) ----
#pragma unroll
    for (int mt = 0; mt < 2; mt++) {
#pragma unroll
        for (int nt = 0; nt < 8; nt++) {
            int col = n0 + nt * 8 + 2 * tg;
            float bb0 = smf[SH_B1 / 4 + col], bb1 = smf[SH_B1 / 4 + col + 1];
            int r0 = m0 + mt * 16 + g;
            __half2 h0 = __floats2half2_rn(fmaxf(acc[mt][nt][0] + bb0, 0.f),
                                           fmaxf(acc[mt][nt][1] + bb1, 0.f));
            __half2 h1 = __floats2half2_rn(fmaxf(acc[mt][nt][2] + bb0, 0.f),
                                           fmaxf(acc[mt][nt][3] + bb1, 0.f));
            *(__half2*)(smb + SH_H1 + r0 * 528 + col * 2) = h0;
            *(__half2*)(smb + SH_H1 + (r0 + 8) * 528 + col * 2) = h1;
        }
    }
    cpa_wait0();       // W2T resident
    __syncthreads();

    // ---- layer 2: C[32][64] per warp over full K=256 (W2T resident) ----
#pragma unroll
    for (int mt = 0; mt < 2; mt++)
#pragma unroll
        for (int nt = 0; nt < 8; nt++)
#pragma unroll
            for (int r = 0; r < 4; r++) acc[mt][nt][r] = 0.f;
    {
        const uint32_t aBase = A0 + SH_H1 + (m0 + (lane & 15)) * 528 + (lane >> 4) * 16;
        const uint32_t bBase = A0 + SH_W2 + (n0 + (lane & 7) + (lane >> 4) * 8) * 528 +
                               ((lane >> 3) & 1) * 16;
#pragma unroll
        for (int ks = 0; ks < NH / 16; ks++) {
            const int k2 = ks * 32;
            uint32_t a[2][4];
            ldsm4(a[0][0], a[0][1], a[0][2], a[0][3], aBase + k2);
            ldsm4(a[1][0], a[1][1], a[1][2], a[1][3], aBase + 16 * 528 + k2);
#pragma unroll
            for (int q = 0; q < 4; q++) {
                uint32_t b0, b1r, b2r, b3r;
                ldsm4(b0, b1r, b2r, b3r, bBase + q * 16 * 528 + k2);
                mma16816(acc[0][2 * q], a[0], b0, b1r);
                mma16816(acc[1][2 * q], a[1], b0, b1r);
                mma16816(acc[0][2 * q + 1], a[0], b2r, b3r);
                mma16816(acc[1][2 * q + 1], a[1], b2r, b3r);
            }
        }
    }

    // ---- fused layer 3 partials: part[row][o] += relu(c+b2[j]) * W3[j][o] ----
    float part[4][4];
#pragma unroll
    for (int r = 0; r < 4; r++)
#pragma unroll
        for (int o = 0; o < 4; o++) part[r][o] = 0.f;
#pragma unroll
    for (int mt = 0; mt < 2; mt++) {
#pragma unroll
        for (int nt = 0; nt < 8; nt++) {
#pragma unroll
            for (int cc = 0; cc < 4; cc++) {
                int j = n0 + nt * 8 + 2 * tg + (cc & 1);
                int r = mt * 2 + (cc >> 1);
                float h = fmaxf(acc[mt][nt][cc] + smf[SH_B2 / 4 + j], 0.f);
#pragma unroll
                for (int o = 0; o < 4; o++)
                    part[r][o] = fmaf(h, smf[SH_W3 / 4 + j * 4 + o], part[r][o]);
            }
        }
    }
    __syncthreads();   // H1 reads done (PART overlays nothing, but keep phase clean)

    // ---- reduce tg lanes, stage per-ng partials ----
#pragma unroll
    for (int r = 0; r < 4; r++)
#pragma unroll
        for (int o = 0; o < 4; o++) {
            part[r][o] += __shfl_xor_sync(0xFFFFFFFFu, part[r][o], 1);
            part[r][o] += __shfl_xor_sync(0xFFFFFFFFu, part[r][o], 2);
        }
    if (tg == 0) {
#pragma unroll
        for (int r = 0; r < 4; r++) {
            int row = m0 + (r >> 1) * 16 + (r & 1) * 8 + g;
#pragma unroll
            for (int o = 0; o < 4; o++)
                smf[SH_PART / 4 + (ng * TILE_P + row) * 4 + o] = part[r][o];
        }
    }
    __syncthreads();

    // ---- final: out[n] += w * (sum_ng part + b3) ----
    {
        const int p = t >> 2, o = t & 3;
        float v = smf[SH_B3 / 4 + o];
#pragma unroll
        for (int q = 0; q < 4; q++) v += smf[SH_PART / 4 + (q * TILE_P + p) * 4 + o];
        if (p < np) {
            int n = sIdx[p];
            atomicAdd(&out[n * 4 + o], g_w[n * NE + e] * v);
        }
    }
}

// -------- launch --------
extern "C" void kernel_launch(void* const* d_in, const int* in_sizes, int n_in,
                              void* d_out, int out_size) {
    const float* x    = (const float*)d_in[0];
    const float* cent = (const float*)d_in[1];
    const float* W1   = (const float*)d_in[2];
    const float* b1   = (const float*)d_in[3];
    const float* W2   = (const float*)d_in[4];
    const float* b2   = (const float*)d_in[5];
    const float* W3   = (const float*)d_in[6];
    const float* b3   = (const float*)d_in[7];
    float* out = (float*)d_out;

    cudaFuncSetAttribute(mlp_mma_kernel, cudaFuncAttributeMaxDynamicSharedMemorySize,
                         SMEM_BYTES);

    zero_cnt_kernel<<<1, 32>>>();
    routing_kernel<<<NPTS / 256, 256>>>(x, cent, out);
    convert_kernel<<<(CONV_TOTAL + 255) / 256, 256>>>(x, W1, W2);
    mlp_mma_kernel<<<BLOCKS, THREADS, SMEM_BYTES>>>(b1, b2, W3, b3, out);
}

// round 6
// speedup vs baseline: 9.5398x; 1.5055x over previous
#include <cuda_runtime.h>
#include <cuda_fp16.h>
#include <cstdint>

#define NPTS 65536
#define NE 8
#define DIN 90
#define NH 256
#define DOUT 4
#define XROW 93
#define TILE_P 128
#define KPAD 96
#define THREADS 256
#define GRID_P 148

// smem byte offsets (strides 208B=13*16, 528B=33*16 -> ldmatrix conflict-free)
#define SH_W1   0           // W1T [256][104h]    53,248B
#define SH_W2   53248       // W2T [256][264h]   135,168B
#define SH_W3T  188416      // W3T [16][264h]      8,448B (rows 0-3 data, 4-15 zero)
#define SH_F    196864      // F   [128][104h]    26,624B
#define SH_B1   223488      // b1 f32 [256]
#define SH_B2   224512      // b2 f32 [256]
#define SH_B3   225536      // b3 f32 [4]
#define SH_IDX  225552      // idx [2][128] int
#define SMEM_BYTES 226576

// -------- device scratch --------
__device__ float  g_w[NPTS * NE];
__device__ int    g_idx[NE * NPTS];
__device__ int    g_cnt[NE];
__device__ int    g_tprefix[NE + 1];
__device__ __half g_xh[NPTS * KPAD];
__device__ __half g_w1t[NE * NH * KPAD];
__device__ __half g_w2t[NE * NH * NH];

#define CONV_TOTAL (NPTS * KPAD + NE * NH * KPAD + NE * NH * NH)

// -------- PTX helpers --------
__device__ __forceinline__ uint32_t smem_u32(const void* p) {
    uint32_t a;
    asm("{ .reg .u64 t; cvta.to.shared.u64 t, %1; cvt.u32.u64 %0, t; }" : "=r"(a) : "l"(p));
    return a;
}
__device__ __forceinline__ void ldsm4(uint32_t& r0, uint32_t& r1, uint32_t& r2, uint32_t& r3,
                                      uint32_t addr) {
    asm volatile("ldmatrix.sync.aligned.m8n8.x4.shared.b16 {%0,%1,%2,%3}, [%4];"
                 : "=r"(r0), "=r"(r1), "=r"(r2), "=r"(r3) : "r"(addr));
}
__device__ __forceinline__ void mma16816(float* c, const uint32_t* a, uint32_t b0, uint32_t b1) {
    asm volatile(
        "mma.sync.aligned.m16n8k16.row.col.f32.f16.f16.f32 "
        "{%0,%1,%2,%3}, {%4,%5,%6,%7}, {%8,%9}, {%0,%1,%2,%3};"
        : "+f"(c[0]), "+f"(c[1]), "+f"(c[2]), "+f"(c[3])
        : "r"(a[0]), "r"(a[1]), "r"(a[2]), "r"(a[3]), "r"(b0), "r"(b1));
}
__device__ __forceinline__ void cpa16(uint32_t dst, const void* src) {
    asm volatile("cp.async.cg.shared.global [%0], [%1], 16;" :: "r"(dst), "l"(src));
}
__device__ __forceinline__ void cpa_commit() { asm volatile("cp.async.commit_group;"); }
__device__ __forceinline__ void cpa_wait0() { asm volatile("cp.async.wait_group 0;" ::: "memory"); }
__device__ __forceinline__ uint32_t pack2(float a, float b) {
    __half2 h = __floats2half2_rn(a, b);
    return *(uint32_t*)&h;
}

// -------- kernel 0: counters --------
__global__ void zero_cnt_kernel() {
    if (threadIdx.x < NE) g_cnt[threadIdx.x] = 0;
}

// -------- kernel 1: routing + compaction + out zero --------
__global__ void routing_kernel(const float* __restrict__ x,
                               const float* __restrict__ cent,
                               float* __restrict__ out) {
    int n = blockIdx.x * blockDim.x + threadIdx.x;
    if (n >= NPTS) return;
    const float px = x[n * XROW + 0];
    const float py = x[n * XROW + 1];
    const float pz = x[n * XROW + 2];
    float d[NE];
    float dmin = 3.4e38f;
#pragma unroll
    for (int e = 0; e < NE; e++) {
        float dx = px - cent[e * 3 + 0];
        float dy = py - cent[e * 3 + 1];
        float dz = pz - cent[e * 3 + 2];
        d[e] = sqrtf(dx * dx + dy * dy + dz * dz);
        dmin = fminf(dmin, d[e]);
    }
    float inv[NE];
    float s = 0.f;
#pragma unroll
    for (int e = 0; e < NE; e++) {
        float v = 1.0f / (d[e] + 1e-8f);
        if (d[e] > 2.0f * dmin) v = 0.f;
        inv[e] = v;
        s += v;
    }
    float rs = 1.0f / s;
#pragma unroll
    for (int e = 0; e < NE; e++) {
        float w = inv[e] * rs;
        g_w[n * NE + e] = w;
        if (w > 0.f) {
            int pos = atomicAdd(&g_cnt[e], 1);
            g_idx[e * NPTS + pos] = n;
        }
    }
    *reinterpret_cast<float4*>(out + n * 4) = make_float4(0.f, 0.f, 0.f, 0.f);
}

// -------- kernel 1b: fp16 pre-convert --------
__global__ void convert_kernel(const float* __restrict__ x,
                               const float* __restrict__ W1,
                               const float* __restrict__ W2) {
    int i = blockIdx.x * blockDim.x + threadIdx.x;
    if (i < NPTS * KPAD) {
        int n = i / KPAD, k = i - n * KPAD;
        g_xh[i] = (k < DIN) ? __float2half_rn(x[n * XROW + 3 + k]) : __half(0.f);
    } else if (i < NPTS * KPAD + NE * NH * KPAD) {
        int r = i - NPTS * KPAD;
        int e = r / (NH * KPAD);
        int rr = r - e * NH * KPAD;
        int n = rr / KPAD, k = rr - n * KPAD;
        g_w1t[r] = (k < DIN) ? __float2half_rn(W1[(e * DIN + k) * NH + n]) : __half(0.f);
    } else if (i < CONV_TOTAL) {
        int r = i - NPTS * KPAD - NE * NH * KPAD;
        int e = r >> 16;
        int rr = r & 65535;
        int n = rr >> 8, k = rr & 255;
        g_w2t[r] = __float2half_rn(W2[(e << 16) + (k << 8) + n]);
    }
}

// -------- kernel 1c: tile prefix --------
__global__ void prefix_kernel() {
    if (threadIdx.x == 0) {
        int run = 0;
#pragma unroll
        for (int e = 0; e < NE; e++) {
            g_tprefix[e] = run;
            run += (g_cnt[e] + TILE_P - 1) / TILE_P;
        }
        g_tprefix[NE] = run;
    }
}

// -------- tile prefetch: idx + F rows via cp.async --------
__device__ __forceinline__ void prefetch_tile(uint32_t A0, char* smb, int e, int base,
                                              int cnt, int ibuf, int t) {
    if (t < TILE_P) {
        int gi = base + t;
        int idxv = (gi < cnt) ? g_idx[e * NPTS + gi] : -1;
        ((int*)(smb + SH_IDX))[ibuf * TILE_P + t] = idxv;
        int real = idxv < 0 ? 0 : idxv;
        const char* src = (const char*)(g_xh + (size_t)real * KPAD);
        uint32_t dst = A0 + SH_F + t * 208;
#pragma unroll
        for (int j = 0; j < 12; j++) cpa16(dst + j * 16, src + j * 16);
    }
}

// -------- expert weight load --------
__device__ __forceinline__ void load_expert(uint32_t A0, char* smb, int e, int t,
                                            const float* b1, const float* b2,
                                            const float* W3, const float* b3) {
    {
        const char* src = (const char*)(g_w1t + ((size_t)e * NH + t) * KPAD);
        uint32_t dst = A0 + SH_W1 + t * 208;
#pragma unroll
        for (int j = 0; j < 12; j++) cpa16(dst + j * 16, src + j * 16);
    }
    {
        const char* src = (const char*)(g_w2t + ((size_t)e * NH + t) * NH);
        uint32_t dst = A0 + SH_W2 + t * 528;
#pragma unroll
        for (int j = 0; j < 32; j++) cpa16(dst + j * 16, src + j * 16);
    }
    if (t < 64) cpa16(A0 + SH_B1 + t * 16, (const char*)(b1 + e * NH) + t * 16);
    else if (t < 128) cpa16(A0 + SH_B2 + (t - 64) * 16, (const char*)(b2 + e * NH) + (t - 64) * 16);
    {
        __half* w3t = (__half*)(smb + SH_W3T);
        for (int i = t; i < 12 * 256; i += THREADS) {       // zero rows 4..15
            int r = i >> 8, k = i & 255;
            w3t[(4 + r) * 264 + k] = __half(0.f);
        }
        for (int i = t; i < 4 * 256; i += THREADS) {        // rows 0..3 = W3^T
            int o = i >> 8, k = i & 255;
            w3t[o * 264 + k] = __float2half_rn(W3[e * NH * DOUT + k * DOUT + o]);
        }
    }
    if (t < 4) ((float*)(smb + SH_B3))[t] = b3[e * DOUT + t];
}

// -------- kernel 2: persistent fused MLP --------
__global__ __launch_bounds__(THREADS, 1)
void mlp_persist_kernel(const float* __restrict__ b1, const float* __restrict__ b2,
                        const float* __restrict__ W3, const float* __restrict__ b3,
                        float* __restrict__ out) {
    int tp[NE + 1];
#pragma unroll
    for (int i = 0; i <= NE; i++) tp[i] = g_tprefix[i];
    const int total = tp[NE];
    const int G = gridDim.x;
    const int lo = (int)(((long long)blockIdx.x * total) / G);
    const int hi = (int)(((long long)(blockIdx.x + 1) * total) / G);
    if (lo >= hi) return;

    extern __shared__ char smb[];
    const uint32_t A0 = smem_u32(smb);
    const int t = threadIdx.x;
    const int wid = t >> 5, lane = t & 31;
    const int g = lane >> 2, tg = lane & 3;
    const int m0 = wid * 16;

    const uint32_t aBase = A0 + SH_F + (m0 + (lane & 15)) * 208 + (lane >> 4) * 16;
    const uint32_t rowpat = (uint32_t)((lane & 7) + ((lane >> 4) << 3));
    const uint32_t colpat = (uint32_t)(((lane >> 3) & 1) * 16);
    const uint32_t bRow1 = A0 + SH_W1 + rowpat * 208 + colpat;
    const uint32_t bRow2 = A0 + SH_W2 + rowpat * 528 + colpat;
    const uint32_t wRow3 = A0 + SH_W3T + rowpat * 528 + colpat;

    int cur_e = -1;
    int cbuf = 0;
    {
        int e0 = 0;
#pragma unroll
        for (int k = 1; k < NE; k++) if (lo >= tp[k]) e0 = k;
        prefetch_tile(A0, smb, e0, (lo - tp[e0]) * TILE_P, g_cnt[e0], 0, t);
        cpa_commit();
    }

    for (int tt = lo; tt < hi; tt++) {
        int e = 0;
#pragma unroll
        for (int k = 1; k < NE; k++) if (tt >= tp[k]) e = k;

        cpa_wait0();
        __syncthreads();                       // F(tt)+idx ready; prev tile done
        if (e != cur_e) {
            load_expert(A0, smb, e, t, b1, b2, W3, b3);
            cpa_commit();
            cpa_wait0();
            __syncthreads();
            cur_e = e;
        }

        // ---- A1 fragment preload (F then free) ----
        uint32_t A1[6][4];
#pragma unroll
        for (int s = 0; s < 6; s++)
            ldsm4(A1[s][0], A1[s][1], A1[s][2], A1[s][3], aBase + s * 32);
        __syncthreads();                       // F buffer free

        if (tt + 1 < hi) {
            int e2 = 0;
#pragma unroll
            for (int k = 1; k < NE; k++) if (tt + 1 >= tp[k]) e2 = k;
            prefetch_tile(A0, smb, e2, (tt + 1 - tp[e2]) * TILE_P, g_cnt[e2], cbuf ^ 1, t);
            cpa_commit();
        }

        // ---- layer 1: hA = fp16 A-fragments of relu(F@W1^T + b1) ----
        uint32_t hA[64];
#pragma unroll
        for (int qpp = 0; qpp < 8; qpp++) {
            float C[16];
#pragma unroll
            for (int i = 0; i < 16; i++) C[i] = 0.f;
            uint32_t bbA = bRow1 + (qpp * 32) * 208;
            uint32_t bbB = bbA + 16 * 208;
            uint32_t bf[2][8];
            ldsm4(bf[0][0], bf[0][1], bf[0][2], bf[0][3], bbA);
            ldsm4(bf[0][4], bf[0][5], bf[0][6], bf[0][7], bbB);
#pragma unroll
            for (int s = 0; s < 6; s++) {
                int cu = s & 1;
                if (s < 5) {
                    ldsm4(bf[cu ^ 1][0], bf[cu ^ 1][1], bf[cu ^ 1][2], bf[cu ^ 1][3],
                          bbA + (s + 1) * 32);
                    ldsm4(bf[cu ^ 1][4], bf[cu ^ 1][5], bf[cu ^ 1][6], bf[cu ^ 1][7],
                          bbB + (s + 1) * 32);
                }
                mma16816(C + 0,  A1[s], bf[cu][0], bf[cu][1]);
                mma16816(C + 4,  A1[s], bf[cu][2], bf[cu][3]);
                mma16816(C + 8,  A1[s], bf[cu][4], bf[cu][5]);
                mma16816(C + 12, A1[s], bf[cu][6], bf[cu][7]);
            }
#pragma unroll
            for (int h = 0; h < 2; h++) {
                int colb = 32 * qpp + 16 * h;
                float2 ba = *(float2*)(smb + SH_B1 + (colb + 2 * tg) * 4);
                float2 bb = *(float2*)(smb + SH_B1 + (colb + 8 + 2 * tg) * 4);
                const float* Cc = C + 8 * h;
                hA[8 * qpp + 4 * h + 0] = pack2(fmaxf(Cc[0] + ba.x, 0.f), fmaxf(Cc[1] + ba.y, 0.f));
                hA[8 * qpp + 4 * h + 1] = pack2(fmaxf(Cc[2] + ba.x, 0.f), fmaxf(Cc[3] + ba.y, 0.f));
                hA[8 * qpp + 4 * h + 2] = pack2(fmaxf(Cc[4] + bb.x, 0.f), fmaxf(Cc[5] + bb.y, 0.f));
                hA[8 * qpp + 4 * h + 3] = pack2(fmaxf(Cc[6] + bb.x, 0.f), fmaxf(Cc[7] + bb.y, 0.f));
            }
        }

        // ---- layer 2 + fused layer-3 mma ----
        float C3[4] = {0.f, 0.f, 0.f, 0.f};
#pragma unroll
        for (int qpp = 0; qpp < 8; qpp++) {
            float C[16];
#pragma unroll
            for (int i = 0; i < 16; i++) C[i] = 0.f;
            uint32_t bbA = bRow2 + (qpp * 32) * 528;
            uint32_t bbB = bbA + 16 * 528;
            uint32_t bf[2][8];
            ldsm4(bf[0][0], bf[0][1], bf[0][2], bf[0][3], bbA);
            ldsm4(bf[0][4], bf[0][5], bf[0][6], bf[0][7], bbB);
#pragma unroll
            for (int s = 0; s < 16; s++) {
                int cu = s & 1;
                if (s < 15) {
                    ldsm4(bf[cu ^ 1][0], bf[cu ^ 1][1], bf[cu ^ 1][2], bf[cu ^ 1][3],
                          bbA + (s + 1) * 32);
                    ldsm4(bf[cu ^ 1][4], bf[cu ^ 1][5], bf[cu ^ 1][6], bf[cu ^ 1][7],
                          bbB + (s + 1) * 32);
                }
                mma16816(C + 0,  &hA[4 * s], bf[cu][0], bf[cu][1]);
                mma16816(C + 4,  &hA[4 * s], bf[cu][2], bf[cu][3]);
                mma16816(C + 8,  &hA[4 * s], bf[cu][4], bf[cu][5]);
                mma16816(C + 12, &hA[4 * s], bf[cu][6], bf[cu][7]);
            }
#pragma unroll
            for (int h = 0; h < 2; h++) {
                int colb = 32 * qpp + 16 * h;
                float2 ba = *(float2*)(smb + SH_B2 + (colb + 2 * tg) * 4);
                float2 bb = *(float2*)(smb + SH_B2 + (colb + 8 + 2 * tg) * 4);
                const float* Cc = C + 8 * h;
                uint32_t a2[4];
                a2[0] = pack2(fmaxf(Cc[0] + ba.x, 0.f), fmaxf(Cc[1] + ba.y, 0.f));
                a2[1] = pack2(fmaxf(Cc[2] + ba.x, 0.f), fmaxf(Cc[3] + ba.y, 0.f));
                a2[2] = pack2(fmaxf(Cc[4] + bb.x, 0.f), fmaxf(Cc[5] + bb.y, 0.f));
                a2[3] = pack2(fmaxf(Cc[6] + bb.x, 0.f), fmaxf(Cc[7] + bb.y, 0.f));
                uint32_t w0, w1r, w2r, w3r;
                ldsm4(w0, w1r, w2r, w3r, wRow3 + (2 * qpp + h) * 32);
                mma16816(C3, a2, w0, w1r);
            }
        }

        // ---- weighted scatter (C3 cols 0-3 valid; rows g, g+8) ----
        if (tg < 2) {
            const int* sIdxCur = (const int*)(smb + SH_IDX) + cbuf * TILE_P;
            const float* sb3 = (const float*)(smb + SH_B3);
            int col = 2 * tg;
            float b3a = sb3[col], b3b = sb3[col + 1];
            int n0i = sIdxCur[m0 + g];
            int n1i = sIdxCur[m0 + g + 8];
            if (n0i >= 0) {
                float w = g_w[n0i * NE + e];
                atomicAdd(&out[n0i * 4 + col],     w * (C3[0] + b3a));
                atomicAdd(&out[n0i * 4 + col + 1], w * (C3[1] + b3b));
            }
            if (n1i >= 0) {
                float w = g_w[n1i * NE + e];
                atomicAdd(&out[n1i * 4 + col],     w * (C3[2] + b3a));
                atomicAdd(&out[n1i * 4 + col + 1], w * (C3[3] + b3b));
            }
        }
        cbuf ^= 1;
    }
}

// -------- launch --------
extern "C" void kernel_launch(void* const* d_in, const int* in_sizes, int n_in,
                              void* d_out, int out_size) {
    const float* x    = (const float*)d_in[0];
    const float* cent = (const float*)d_in[1];
    const float* W1   = (const float*)d_in[2];
    const float* b1   = (const float*)d_in[3];
    const float* W2   = (const float*)d_in[4];
    const float* b2   = (const float*)d_in[5];
    const float* W3   = (const float*)d_in[6];
    const float* b3   = (const float*)d_in[7];
    float* out = (float*)d_out;

    cudaFuncSetAttribute(mlp_persist_kernel, cudaFuncAttributeMaxDynamicSharedMemorySize,
                         SMEM_BYTES);

    zero_cnt_kernel<<<1, 32>>>();
    routing_kernel<<<NPTS / 256, 256>>>(x, cent, out);
    convert_kernel<<<(CONV_TOTAL + 255) / 256, 256>>>(x, W1, W2);
    prefix_kernel<<<1, 32>>>();
    mlp_persist_kernel<<<GRID_P, THREADS, SMEM_BYTES>>>(b1, b2, W3, b3, out);
}